// round 7
// baseline (speedup 1.0000x reference)
#include <cuda_runtime.h>
#include <cuda_bf16.h>

#define N_NODES 50000
#define D_FEAT  128

// CSR row offsets into the sorted edge list. 50001 ints.
__device__ int g_offsets[N_NODES + 1];

// Kernel A: boundary-diff scatter. edge_src is sorted; thread e fills
// offsets[n] = e for all n in (edge_src[e-1], edge_src[e]].
__global__ void build_offsets_kernel(const int* __restrict__ edge_src, int n_edges) {
    int e = blockIdx.x * blockDim.x + threadIdx.x;
    if (e >= n_edges) return;
    int s1 = edge_src[e];
    int s0 = (e == 0) ? -1 : edge_src[e - 1];
    for (int n = s0 + 1; n <= s1; n++) g_offsets[n] = e;
    if (e == n_edges - 1) {
        for (int n = s1 + 1; n <= N_NODES; n++) g_offsets[n] = n_edges;
    }
}

// Kernel B: one warp per node, predicated unroll-4 — no scalar tail.
// Every node runs ceil(deg/4) iterations, all gathers at MLP<=4; slots past
// `end` are @!P no-op loads contributing zero.
__global__ void __launch_bounds__(128)
graph_pool_kernel(const float4* __restrict__ x,
                  const int* __restrict__ edge_dst,
                  float4* __restrict__ out) {
    int warp_id = (blockIdx.x * blockDim.x + threadIdx.x) >> 5;
    int lane = threadIdx.x & 31;
    if (warp_id >= N_NODES) return;

    int beg = g_offsets[warp_id];
    int end = g_offsets[warp_id + 1];

    // self feature
    float4 acc = x[(size_t)warp_id * 32 + lane];

    for (int e = beg; e < end; e += 4) {
        bool p1 = (e + 1) < end;
        bool p2 = (e + 2) < end;
        bool p3 = (e + 3) < end;
        int d0 = edge_dst[e];
        int d1 = p1 ? edge_dst[e + 1] : 0;
        int d2 = p2 ? edge_dst[e + 2] : 0;
        int d3 = p3 ? edge_dst[e + 3] : 0;

        float4 v0 = __ldg(&x[(size_t)d0 * 32 + lane]);
        float4 v1 = make_float4(0.f, 0.f, 0.f, 0.f);
        float4 v2 = make_float4(0.f, 0.f, 0.f, 0.f);
        float4 v3 = make_float4(0.f, 0.f, 0.f, 0.f);
        if (p1) v1 = __ldg(&x[(size_t)d1 * 32 + lane]);
        if (p2) v2 = __ldg(&x[(size_t)d2 * 32 + lane]);
        if (p3) v3 = __ldg(&x[(size_t)d3 * 32 + lane]);

        acc.x += v0.x; acc.y += v0.y; acc.z += v0.z; acc.w += v0.w;
        acc.x += v1.x; acc.y += v1.y; acc.z += v1.z; acc.w += v1.w;
        acc.x += v2.x; acc.y += v2.y; acc.z += v2.z; acc.w += v2.w;
        acc.x += v3.x; acc.y += v3.y; acc.z += v3.z; acc.w += v3.w;
    }

    out[(size_t)warp_id * 32 + lane] = acc;
}

extern "C" void kernel_launch(void* const* d_in, const int* in_sizes, int n_in,
                              void* d_out, int out_size) {
    const float* x = (const float*)d_in[0];
    const int* edge_src = (const int*)d_in[1];
    const int* edge_dst = (const int*)d_in[2];
    float* out = (float*)d_out;
    int n_edges = in_sizes[1];

    // Kernel A: O(E) boundary-diff offsets
    {
        int threads = 256;
        int blocks = (n_edges + threads - 1) / threads;
        build_offsets_kernel<<<blocks, threads>>>(edge_src, n_edges);
    }

    // Kernel B: one warp per node, 4 warps per block
    {
        int threads = 128;
        int warps_per_block = threads / 32;
        int blocks = (N_NODES + warps_per_block - 1) / warps_per_block;
        graph_pool_kernel<<<blocks, threads>>>((const float4*)x, edge_dst,
                                               (float4*)out);
    }
}